// round 6
// baseline (speedup 1.0000x reference)
#include <cuda_runtime.h>
#include <cuda_bf16.h>

#define THREADS 256
#define SPT 8
#define GRID_P 444

struct Quat { float w, x, y, z; };

// general quaternion product (used in tree combines)
__device__ __forceinline__ Quat qmul(const Quat a, const Quat b) {
    Quat o;
    o.w = a.w * b.w - a.x * b.x - a.y * b.y - a.z * b.z;
    o.x = a.w * b.x + a.x * b.w + a.y * b.z - a.z * b.y;
    o.y = a.w * b.y - a.x * b.z + a.y * b.w + a.z * b.x;
    o.z = a.w * b.z + a.x * b.y - a.y * b.x + a.z * b.w;
    return o;
}

// a * (1, dx, dy, dz)  — 12 FFMA
__device__ __forceinline__ Quat qmul_unit(const Quat a, float dx, float dy, float dz) {
    Quat o;
    o.w = fmaf(-a.x, dx, fmaf(-a.y, dy, fmaf(-a.z, dz, a.w)));
    o.x = fmaf( a.w, dx, fmaf( a.y, dz, fmaf(-a.z, dy, a.x)));
    o.y = fmaf( a.w, dy, fmaf(-a.x, dz, fmaf( a.z, dx, a.y)));
    o.z = fmaf( a.w, dz, fmaf( a.x, dy, fmaf(-a.y, dx, a.z)));
    return o;
}

__global__ __launch_bounds__(THREADS, 3)
void tinygc2l_kernel(const float* __restrict__ ts,
                     const float* __restrict__ gyro,
                     const float* __restrict__ q0g,
                     const float* __restrict__ W1,
                     const float* __restrict__ B1,
                     const float* __restrict__ A1,
                     const float* __restrict__ W2,
                     const float* __restrict__ B2,
                     const float* __restrict__ A2,
                     float* __restrict__ out,
                     int B, int CNT)
{
    __shared__ float4 s_wq[THREADS / 32];

    const int tid  = threadIdx.x;
    const int lane = tid & 31;
    const int wid  = tid >> 5;
    const int t0   = tid * SPT;

    // ---- weights once per CTA lifetime ----
    float w1[9], w2[9], bb1[3], bb2[3];
    #pragma unroll
    for (int i = 0; i < 9; i++) { w1[i] = __ldg(W1 + i); w2[i] = __ldg(W2 + i); }
    #pragma unroll
    for (int i = 0; i < 3; i++) { bb1[i] = __ldg(B1 + i); bb2[i] = __ldg(B2 + i); }
    const float a1 = __ldg(A1);
    const float a2 = __ldg(A2);
    // prelu(x) = c1*x + c2*|x|
    const float c1a = 0.5f * (1.f + a1), c2a = 0.5f * (1.f - a1);
    const float c1b = 0.5f * (1.f + a2), c2b = 0.5f * (1.f - a2);

    // tiny-net: (ix,iy,iz) -> residual-corrected g
    auto mlp = [&](float ix, float iy, float iz, float& gx, float& gy, float& gz) {
        float h0 = fmaf(w1[0], ix, fmaf(w1[1], iy, fmaf(w1[2], iz, bb1[0])));
        float h1 = fmaf(w1[3], ix, fmaf(w1[4], iy, fmaf(w1[5], iz, bb1[1])));
        float h2 = fmaf(w1[6], ix, fmaf(w1[7], iy, fmaf(w1[8], iz, bb1[2])));
        h0 = fmaf(c2a, fabsf(h0), c1a * h0);
        h1 = fmaf(c2a, fabsf(h1), c1a * h1);
        h2 = fmaf(c2a, fabsf(h2), c1a * h2);
        float g0 = fmaf(w2[0], h0, fmaf(w2[1], h1, fmaf(w2[2], h2, bb2[0])));
        float g1 = fmaf(w2[3], h0, fmaf(w2[4], h1, fmaf(w2[5], h2, bb2[1])));
        float g2 = fmaf(w2[6], h0, fmaf(w2[7], h1, fmaf(w2[8], h2, bb2[2])));
        g0 = fmaf(c2b, fabsf(g0), c1b * g0);
        g1 = fmaf(c2b, fabsf(g1), c1b * g1);
        g2 = fmaf(c2b, fabsf(g2), c1b * g2);
        gx = g0 + ix; gy = g1 + iy; gz = g2 + iz;
    };

    for (int b = blockIdx.x; b < B; b += gridDim.x) {
        __syncthreads();   // protect s_wq across row iterations

        // ---- vectorized global->register tile load ----
        float gf[27];      // 8 owned points + boundary point 8
        float tf[9];
        {
            const float4* gsrc = reinterpret_cast<const float4*>(
                gyro + (size_t)b * CNT * 3 + (size_t)t0 * 3);
            #pragma unroll
            for (int i = 0; i < 6; i++) {
                float4 v = gsrc[i];
                gf[4 * i + 0] = v.x; gf[4 * i + 1] = v.y;
                gf[4 * i + 2] = v.z; gf[4 * i + 3] = v.w;
            }
            const float4* tsrc = reinterpret_cast<const float4*>(
                ts + (size_t)b * CNT + t0);
            #pragma unroll
            for (int i = 0; i < 2; i++) {
                float4 v = tsrc[i];
                tf[4 * i + 0] = v.x; tf[4 * i + 1] = v.y;
                tf[4 * i + 2] = v.z; tf[4 * i + 3] = v.w;
            }
        }

        // ---- tiny-net on the 8 owned points (in place) ----
        #pragma unroll
        for (int i = 0; i < 8; i++)
            mlp(gf[3 * i], gf[3 * i + 1], gf[3 * i + 2],
                gf[3 * i], gf[3 * i + 1], gf[3 * i + 2]);

        // ---- boundary point 8 from neighbor thread via shfl ----
        {
            float g8x = __shfl_down_sync(0xffffffffu, gf[0], 1);
            float g8y = __shfl_down_sync(0xffffffffu, gf[1], 1);
            float g8z = __shfl_down_sync(0xffffffffu, gf[2], 1);
            float t8  = __shfl_down_sync(0xffffffffu, tf[0], 1);
            if (lane == 31 && t0 + 8 <= CNT - 1) {
                // inter-warp boundary: load + compute directly
                const float* gp8 = gyro + (size_t)b * CNT * 3 + (size_t)(t0 + 8) * 3;
                mlp(gp8[0], gp8[1], gp8[2], g8x, g8y, g8z);
                t8 = ts[(size_t)b * CNT + t0 + 8];
            }
            gf[24] = g8x; gf[25] = g8y; gf[26] = g8z;
            tf[8] = t8;
        }

        // ---- ordered per-thread product (12-FMA unit steps) ----
        const int nsteps = max(0, min(SPT, (CNT - 1) - t0));
        Quat p; p.w = 1.f; p.x = 0.f; p.y = 0.f; p.z = 0.f;
        #pragma unroll
        for (int i = 0; i < SPT; i++) {
            if (i < nsteps) {
                const float s = 0.25f * (tf[i + 1] - tf[i]);
                const float dx = (gf[3 * i + 0] + gf[3 * i + 3]) * s;
                const float dy = (gf[3 * i + 1] + gf[3 * i + 4]) * s;
                const float dz = (gf[3 * i + 2] + gf[3 * i + 5]) * s;
                p = qmul_unit(p, dx, dy, dz);
            }
        }
        {
            const float n2 = p.w * p.w + p.x * p.x + p.y * p.y + p.z * p.z;
            const float inv = rsqrtf(fmaxf(n2, 1e-24f));
            p.w *= inv; p.x *= inv; p.y *= inv; p.z *= inv;
        }

        // ---- ordered warp tree reduction ----
        #pragma unroll
        for (int off = 1; off < 32; off <<= 1) {
            Quat q;
            q.w = __shfl_down_sync(0xffffffffu, p.w, off);
            q.x = __shfl_down_sync(0xffffffffu, p.x, off);
            q.y = __shfl_down_sync(0xffffffffu, p.y, off);
            q.z = __shfl_down_sync(0xffffffffu, p.z, off);
            if (lane + off < 32) p = qmul(p, q);
        }
        if (lane == 0) s_wq[wid] = make_float4(p.w, p.x, p.y, p.z);
        __syncthreads();

        // ---- warp 0: ordered reduce of 8 warp products, finalize ----
        if (wid == 0) {
            Quat r; r.w = 1.f; r.x = 0.f; r.y = 0.f; r.z = 0.f;
            if (lane < THREADS / 32) {
                float4 v = s_wq[lane];
                r.w = v.x; r.x = v.y; r.y = v.z; r.z = v.w;
            }
            #pragma unroll
            for (int off = 1; off < THREADS / 32; off <<= 1) {
                Quat q;
                q.w = __shfl_down_sync(0xffffffffu, r.w, off);
                q.x = __shfl_down_sync(0xffffffffu, r.x, off);
                q.y = __shfl_down_sync(0xffffffffu, r.y, off);
                q.z = __shfl_down_sync(0xffffffffu, r.z, off);
                if (lane + off < THREADS / 32) r = qmul(r, q);
            }
            if (lane == 0) {
                Quat q0;
                const float* qp = q0g + (size_t)b * 4;
                q0.w = qp[0]; q0.x = qp[1]; q0.y = qp[2]; q0.z = qp[3];
                Quat f = qmul(q0, r);
                const float n = sqrtf(f.w * f.w + f.x * f.x + f.y * f.y + f.z * f.z);
                const float inv = 1.0f / fmaxf(n, 1e-12f);
                float* op = out + (size_t)b * 4;
                op[0] = f.w * inv;
                op[1] = f.x * inv;
                op[2] = f.y * inv;
                op[3] = f.z * inv;
            }
        }
    }
}

extern "C" void kernel_launch(void* const* d_in, const int* in_sizes, int n_in,
                              void* d_out, int out_size) {
    const float* ts   = (const float*)d_in[0];
    const float* gyro = (const float*)d_in[1];
    const float* q0   = (const float*)d_in[2];
    const float* W1   = (const float*)d_in[3];
    const float* b1   = (const float*)d_in[4];
    const float* a1   = (const float*)d_in[5];
    const float* W2   = (const float*)d_in[6];
    const float* b2   = (const float*)d_in[7];
    const float* a2   = (const float*)d_in[8];
    float* out = (float*)d_out;

    const int B   = in_sizes[2] / 4;   // start_quat is (B,4)
    const int CNT = in_sizes[0] / B;   // timestamps are (B,CNT)

    const int grid = (B < GRID_P) ? B : GRID_P;
    tinygc2l_kernel<<<grid, THREADS>>>(ts, gyro, q0, W1, b1, a1, W2, b2, a2,
                                       out, B, CNT);
}

// round 7
// speedup vs baseline: 1.0052x; 1.0052x over previous
#include <cuda_runtime.h>
#include <cuda_bf16.h>

#define THREADS 256
#define SPT 8

struct Quat { float w, x, y, z; };

// general quaternion product (tree combines)
__device__ __forceinline__ Quat qmul(const Quat a, const Quat b) {
    Quat o;
    o.w = a.w * b.w - a.x * b.x - a.y * b.y - a.z * b.z;
    o.x = a.w * b.x + a.x * b.w + a.y * b.z - a.z * b.y;
    o.y = a.w * b.y - a.x * b.z + a.y * b.w + a.z * b.x;
    o.z = a.w * b.z + a.x * b.y - a.y * b.x + a.z * b.w;
    return o;
}

// a * (1, dx, dy, dz) — 12 FFMA
__device__ __forceinline__ Quat qmul_unit(const Quat a, float dx, float dy, float dz) {
    Quat o;
    o.w = fmaf(-a.x, dx, fmaf(-a.y, dy, fmaf(-a.z, dz, a.w)));
    o.x = fmaf( a.w, dx, fmaf( a.y, dz, fmaf(-a.z, dy, a.x)));
    o.y = fmaf( a.w, dy, fmaf(-a.x, dz, fmaf( a.z, dx, a.y)));
    o.z = fmaf( a.w, dz, fmaf( a.x, dy, fmaf(-a.y, dx, a.z)));
    return o;
}

__global__ __launch_bounds__(THREADS, 3)
void tinygc2l_kernel(const float* __restrict__ ts,
                     const float* __restrict__ gyro,
                     const float* __restrict__ q0g,
                     const float* __restrict__ W1,
                     const float* __restrict__ B1,
                     const float* __restrict__ A1,
                     const float* __restrict__ W2,
                     const float* __restrict__ B2,
                     const float* __restrict__ A2,
                     float* __restrict__ out,
                     int CNT)
{
    __shared__ float4 s_wq[THREADS / 32];

    const int b    = blockIdx.x;
    const int tid  = threadIdx.x;
    const int lane = tid & 31;
    const int wid  = tid >> 5;
    const int t0   = tid * SPT;

    // ---- vectorized global->register tile load (issue FIRST for latency) ----
    float gf[27];      // 8 owned points + boundary point 8
    float tf[9];
    {
        const float4* gsrc = reinterpret_cast<const float4*>(
            gyro + (size_t)b * CNT * 3 + (size_t)t0 * 3);
        #pragma unroll
        for (int i = 0; i < 6; i++) {
            float4 v = gsrc[i];
            gf[4 * i + 0] = v.x; gf[4 * i + 1] = v.y;
            gf[4 * i + 2] = v.z; gf[4 * i + 3] = v.w;
        }
        const float4* tsrc = reinterpret_cast<const float4*>(
            ts + (size_t)b * CNT + t0);
        #pragma unroll
        for (int i = 0; i < 2; i++) {
            float4 v = tsrc[i];
            tf[4 * i + 0] = v.x; tf[4 * i + 1] = v.y;
            tf[4 * i + 2] = v.z; tf[4 * i + 3] = v.w;
        }
    }

    // ---- weights ----
    float w1[9], w2[9], bb1[3], bb2[3];
    #pragma unroll
    for (int i = 0; i < 9; i++) { w1[i] = __ldg(W1 + i); w2[i] = __ldg(W2 + i); }
    #pragma unroll
    for (int i = 0; i < 3; i++) { bb1[i] = __ldg(B1 + i); bb2[i] = __ldg(B2 + i); }
    const float a1 = __ldg(A1);
    const float a2 = __ldg(A2);
    // prelu(x) = c1*x + c2*|x|
    const float c1a = 0.5f * (1.f + a1), c2a = 0.5f * (1.f - a1);
    const float c1b = 0.5f * (1.f + a2), c2b = 0.5f * (1.f - a2);

    auto mlp = [&](float ix, float iy, float iz, float& gx, float& gy, float& gz) {
        float h0 = fmaf(w1[0], ix, fmaf(w1[1], iy, fmaf(w1[2], iz, bb1[0])));
        float h1 = fmaf(w1[3], ix, fmaf(w1[4], iy, fmaf(w1[5], iz, bb1[1])));
        float h2 = fmaf(w1[6], ix, fmaf(w1[7], iy, fmaf(w1[8], iz, bb1[2])));
        h0 = fmaf(c2a, fabsf(h0), c1a * h0);
        h1 = fmaf(c2a, fabsf(h1), c1a * h1);
        h2 = fmaf(c2a, fabsf(h2), c1a * h2);
        float g0 = fmaf(w2[0], h0, fmaf(w2[1], h1, fmaf(w2[2], h2, bb2[0])));
        float g1 = fmaf(w2[3], h0, fmaf(w2[4], h1, fmaf(w2[5], h2, bb2[1])));
        float g2 = fmaf(w2[6], h0, fmaf(w2[7], h1, fmaf(w2[8], h2, bb2[2])));
        g0 = fmaf(c2b, fabsf(g0), c1b * g0);
        g1 = fmaf(c2b, fabsf(g1), c1b * g1);
        g2 = fmaf(c2b, fabsf(g2), c1b * g2);
        gx = g0 + ix; gy = g1 + iy; gz = g2 + iz;
    };

    // ---- tiny-net on the 8 owned points (in place) ----
    #pragma unroll
    for (int i = 0; i < 8; i++)
        mlp(gf[3 * i], gf[3 * i + 1], gf[3 * i + 2],
            gf[3 * i], gf[3 * i + 1], gf[3 * i + 2]);

    // ---- boundary point 8 from neighbor thread via shfl ----
    {
        float g8x = __shfl_down_sync(0xffffffffu, gf[0], 1);
        float g8y = __shfl_down_sync(0xffffffffu, gf[1], 1);
        float g8z = __shfl_down_sync(0xffffffffu, gf[2], 1);
        float t8  = __shfl_down_sync(0xffffffffu, tf[0], 1);
        if (lane == 31 && t0 + 8 <= CNT - 1) {
            // inter-warp boundary: load + compute directly (L1/L2 hit)
            const float* gp8 = gyro + (size_t)b * CNT * 3 + (size_t)(t0 + 8) * 3;
            mlp(gp8[0], gp8[1], gp8[2], g8x, g8y, g8z);
            t8 = ts[(size_t)b * CNT + t0 + 8];
        }
        gf[24] = g8x; gf[25] = g8y; gf[26] = g8z;
        tf[8] = t8;
    }

    // ---- ordered per-thread product (12-FMA unit steps) ----
    const int nsteps = max(0, min(SPT, (CNT - 1) - t0));
    Quat p; p.w = 1.f; p.x = 0.f; p.y = 0.f; p.z = 0.f;
    #pragma unroll
    for (int i = 0; i < SPT; i++) {
        if (i < nsteps) {
            const float s = 0.25f * (tf[i + 1] - tf[i]);
            const float dx = (gf[3 * i + 0] + gf[3 * i + 3]) * s;
            const float dy = (gf[3 * i + 1] + gf[3 * i + 4]) * s;
            const float dz = (gf[3 * i + 2] + gf[3 * i + 5]) * s;
            p = qmul_unit(p, dx, dy, dz);
        }
    }
    {
        const float n2 = p.w * p.w + p.x * p.x + p.y * p.y + p.z * p.z;
        const float inv = rsqrtf(fmaxf(n2, 1e-24f));
        p.w *= inv; p.x *= inv; p.y *= inv; p.z *= inv;
    }

    // ---- ordered warp tree reduction ----
    #pragma unroll
    for (int off = 1; off < 32; off <<= 1) {
        Quat q;
        q.w = __shfl_down_sync(0xffffffffu, p.w, off);
        q.x = __shfl_down_sync(0xffffffffu, p.x, off);
        q.y = __shfl_down_sync(0xffffffffu, p.y, off);
        q.z = __shfl_down_sync(0xffffffffu, p.z, off);
        if (lane + off < 32) p = qmul(p, q);
    }
    if (lane == 0) s_wq[wid] = make_float4(p.w, p.x, p.y, p.z);
    __syncthreads();

    // ---- warp 0: ordered reduce of 8 warp products, finalize ----
    if (wid == 0) {
        Quat r; r.w = 1.f; r.x = 0.f; r.y = 0.f; r.z = 0.f;
        if (lane < THREADS / 32) {
            float4 v = s_wq[lane];
            r.w = v.x; r.x = v.y; r.y = v.z; r.z = v.w;
        }
        #pragma unroll
        for (int off = 1; off < THREADS / 32; off <<= 1) {
            Quat q;
            q.w = __shfl_down_sync(0xffffffffu, r.w, off);
            q.x = __shfl_down_sync(0xffffffffu, r.x, off);
            q.y = __shfl_down_sync(0xffffffffu, r.y, off);
            q.z = __shfl_down_sync(0xffffffffu, r.z, off);
            if (lane + off < THREADS / 32) r = qmul(r, q);
        }
        if (lane == 0) {
            Quat q0;
            const float* qp = q0g + (size_t)b * 4;
            q0.w = qp[0]; q0.x = qp[1]; q0.y = qp[2]; q0.z = qp[3];
            Quat f = qmul(q0, r);
            const float n = sqrtf(f.w * f.w + f.x * f.x + f.y * f.y + f.z * f.z);
            const float inv = 1.0f / fmaxf(n, 1e-12f);
            float* op = out + (size_t)b * 4;
            op[0] = f.w * inv;
            op[1] = f.x * inv;
            op[2] = f.y * inv;
            op[3] = f.z * inv;
        }
    }
}

extern "C" void kernel_launch(void* const* d_in, const int* in_sizes, int n_in,
                              void* d_out, int out_size) {
    const float* ts   = (const float*)d_in[0];
    const float* gyro = (const float*)d_in[1];
    const float* q0   = (const float*)d_in[2];
    const float* W1   = (const float*)d_in[3];
    const float* b1   = (const float*)d_in[4];
    const float* a1   = (const float*)d_in[5];
    const float* W2   = (const float*)d_in[6];
    const float* b2   = (const float*)d_in[7];
    const float* a2   = (const float*)d_in[8];
    float* out = (float*)d_out;

    const int B   = in_sizes[2] / 4;   // start_quat is (B,4)
    const int CNT = in_sizes[0] / B;   // timestamps are (B,CNT)

    tinygc2l_kernel<<<B, THREADS>>>(ts, gyro, q0, W1, b1, a1, W2, b2, a2, out, CNT);
}